// round 5
// baseline (speedup 1.0000x reference)
#include <cuda_runtime.h>
#include <stdint.h>

#define GRID_RES 64
#define BB 8
#define NN 4096
#define KC 18                       // k-chunks per batch -> 144 blocks total
#define CH ((NN + KC - 1) / KC)     // 228 points per chunk
#define TILE 32                     // points staged per smem tile
#define RF_STRIDE 200               // 192 + pad
#define CF_STRIDE 80                // 64 + interleaved pad (conflict-free float4)
#define PART_ELEMS (3 * 64 * 64)    // 12288 per (b, kc)

// scratch: per-(batch, chunk) partial sums (no atomics, deterministic)
__device__ float g_partial[BB * KC * PART_ELEMS];

__device__ __forceinline__ float ex2f(float x) {
    float r;
    asm("ex2.approx.f32 %0, %1;" : "=f"(r) : "f"(x));
    return r;
}

// insert a 4-float gap after every 16 CF columns -> banks of the 4 float4
// groups land on {0-3,20-23,8-11,28-31}: conflict-free
__device__ __forceinline__ int cf_idx(int jx) { return jx + ((jx >> 4) << 2); }

#define ACC_BODY(p)                                                          \
    do {                                                                     \
        const float4 c0 = *(const float4*)&sCF[p][cgp + 0];                  \
        const float4 c1 = *(const float4*)&sCF[p][cgp + 4];                  \
        const float4 c2 = *(const float4*)&sCF[p][cgp + 8];                  \
        const float4 c3 = *(const float4*)&sCF[p][cgp + 12];                 \
        const float r0 = sRF[p][iy];                                         \
        const float r1 = sRF[p][64 + iy];                                    \
        const float r2 = sRF[p][128 + iy];                                   \
        acc[0]  += r0 * c0.x; acc[1]  += r0 * c0.y;                          \
        acc[2]  += r0 * c0.z; acc[3]  += r0 * c0.w;                          \
        acc[4]  += r0 * c1.x; acc[5]  += r0 * c1.y;                          \
        acc[6]  += r0 * c1.z; acc[7]  += r0 * c1.w;                          \
        acc[8]  += r0 * c2.x; acc[9]  += r0 * c2.y;                          \
        acc[10] += r0 * c2.z; acc[11] += r0 * c2.w;                          \
        acc[12] += r0 * c3.x; acc[13] += r0 * c3.y;                          \
        acc[14] += r0 * c3.z; acc[15] += r0 * c3.w;                          \
        acc[16] += r1 * c0.x; acc[17] += r1 * c0.y;                          \
        acc[18] += r1 * c0.z; acc[19] += r1 * c0.w;                          \
        acc[20] += r1 * c1.x; acc[21] += r1 * c1.y;                          \
        acc[22] += r1 * c1.z; acc[23] += r1 * c1.w;                          \
        acc[24] += r1 * c2.x; acc[25] += r1 * c2.y;                          \
        acc[26] += r1 * c2.z; acc[27] += r1 * c2.w;                          \
        acc[28] += r1 * c3.x; acc[29] += r1 * c3.y;                          \
        acc[30] += r1 * c3.z; acc[31] += r1 * c3.w;                          \
        acc[32] += r2 * c0.x; acc[33] += r2 * c0.y;                          \
        acc[34] += r2 * c0.z; acc[35] += r2 * c0.w;                          \
        acc[36] += r2 * c1.x; acc[37] += r2 * c1.y;                          \
        acc[38] += r2 * c1.z; acc[39] += r2 * c1.w;                          \
        acc[40] += r2 * c2.x; acc[41] += r2 * c2.y;                          \
        acc[42] += r2 * c2.z; acc[43] += r2 * c2.w;                          \
        acc[44] += r2 * c3.x; acc[45] += r2 * c3.y;                          \
        acc[46] += r2 * c3.z; acc[47] += r2 * c3.w;                          \
    } while (0)

__global__ __launch_bounds__(256)
void rbf_partial_kernel(const float* __restrict__ xc,
                        const float* __restrict__ yc,
                        const float* __restrict__ tc,
                        const int* __restrict__ mask) {
    const int b = blockIdx.y;
    const int kc = blockIdx.x;
    const int tid = threadIdx.x;

    const float CEXP = -72.13475204444817f;  // -50 * log2(e)
    const float STEP = 2.0f / 63.0f;

    __shared__ float sRF[TILE][RF_STRIDE];   // row factors: wy, y*wy, t*wy (192)
    __shared__ float sCF[TILE][CF_STRIDE];   // col factors: wx (64, interleave-padded)
    __shared__ float sP[TILE][8];            // px, py, y, t, maskf

    float acc[48];
#pragma unroll
    for (int i = 0; i < 48; i++) acc[i] = 0.0f;

    // stage-B mapping: each thread owns (iy, 16-col group) x 3 channels
    const int iy = tid >> 2;
    const int cg = (tid & 3) << 4;
    const int cgp = cf_idx(cg);

    // stage-A role: v<192 -> row factor (channel vc, y-index viy); else col factor jx
    const int v = tid;
    const int vc = v >> 6;
    const int viy = v & 63;
    const float gy = -1.0f + STEP * (float)viy;
    const int jx = v - 192;
    const float gx = -1.0f + STEP * (float)jx;
    const int jxp = (jx >= 0) ? cf_idx(jx) : 0;

    const int p0 = kc * CH;
    const int p1 = min(p0 + CH, NN);

    for (int base = p0; base < p1; base += TILE) {
        const int np = min(TILE, p1 - base);

        if (tid < np) {
            const int n = base + tid;
            sP[tid][0] = xc[(b * NN + n) * 2 + 0];
            sP[tid][1] = xc[(b * NN + n) * 2 + 1];
            sP[tid][2] = yc[b * NN + n];
            sP[tid][3] = tc[b * NN + n];
            // mask arrives as a 4-byte type (int32 or f32 coercion of jax bool);
            // nonzero-word test handles both. True = drop point.
            sP[tid][4] = (mask[b * NN + n] != 0) ? 0.0f : 1.0f;
        }
        __syncthreads();

        if (v < 192) {
            for (int p = 0; p < np; p++) {
                const float dy = sP[p][1] - gy;
                const float wy = ex2f(CEXP * dy * dy);
                float f = sP[p][4];                 // mask folded here
                if (vc) f *= sP[p][vc + 1];         // vc=1 -> y, vc=2 -> t
                sRF[p][v] = wy * f;
            }
        } else {
            for (int p = 0; p < np; p++) {
                const float dx = sP[p][0] - gx;
                sCF[p][jxp] = ex2f(CEXP * dx * dx);
            }
        }
        __syncthreads();

        if (np == TILE) {
#pragma unroll 4
            for (int p = 0; p < TILE; p++) { ACC_BODY(p); }
        } else {
            for (int p = 0; p < np; p++) { ACC_BODY(p); }
        }
        __syncthreads();
    }

    // write partial sums: layout [c][iy][jx] flat = c*4096 + iy*64 + jx
    float* dst = &g_partial[(b * KC + kc) * PART_ELEMS];
#pragma unroll
    for (int c = 0; c < 3; c++) {
#pragma unroll
        for (int k = 0; k < 4; k++) {
            float4 w;
            w.x = acc[c * 16 + k * 4 + 0];
            w.y = acc[c * 16 + k * 4 + 1];
            w.z = acc[c * 16 + k * 4 + 2];
            w.w = acc[c * 16 + k * 4 + 3];
            *(float4*)&dst[c * 4096 + iy * 64 + cg + k * 4] = w;
        }
    }
}

__global__ __launch_bounds__(256)
void rbf_finalize_kernel(float* __restrict__ out) {
    const int idx = blockIdx.x * blockDim.x + threadIdx.x;
    if (idx >= BB * 4096) return;
    const int b = idx >> 12;
    const int g = idx & 4095;

    float s0 = 0.0f, s1 = 0.0f, s2 = 0.0f;
#pragma unroll
    for (int kc = 0; kc < KC; kc++) {
        const float* p = &g_partial[(b * KC + kc) * PART_ELEMS];
        s0 += p[g];
        s1 += p[4096 + g];
        s2 += p[8192 + g];
    }
    const float inv = 1.0f / (s0 + 1e-5f);
    out[b * PART_ELEMS + g] = s0;
    out[b * PART_ELEMS + 4096 + g] = s1 * inv;
    out[b * PART_ELEMS + 8192 + g] = s2 * inv;
}

extern "C" void kernel_launch(void* const* d_in, const int* in_sizes, int n_in,
                              void* d_out, int out_size) {
    const float* xc = (const float*)d_in[0];
    const float* yc = (const float*)d_in[1];
    const float* tc = (const float*)d_in[2];
    const int* mask = (const int*)d_in[3];

    dim3 grid(KC, BB);
    rbf_partial_kernel<<<grid, 256>>>(xc, yc, tc, mask);

    rbf_finalize_kernel<<<(BB * 4096 + 255) / 256, 256>>>((float*)d_out);
}